// round 15
// baseline (speedup 1.0000x reference)
#include <cuda_runtime.h>
#include <cuda_bf16.h>
#include <math.h>
#include <stdint.h>

#define EPSF 1e-5f

__device__ float g_diag[16 * 512 * 64];
__device__ int   g_eraw[16 * 512];

// m16n8k16 bf16 MMA, fp32 accum (baseline PTX, maps to HMMA on sm_103)
#define MMA16816(c, a0,a1,a2,a3, b0,b1)                                   \
    asm volatile("mma.sync.aligned.m16n8k16.row.col.f32.bf16.bf16.f32 "   \
        "{%0,%1,%2,%3}, {%4,%5,%6,%7}, {%8,%9}, {%0,%1,%2,%3};"           \
        : "+f"((c)[0]), "+f"((c)[1]), "+f"((c)[2]), "+f"((c)[3])          \
        : "r"(a0), "r"(a1), "r"(a2), "r"(a3), "r"(b0), "r"(b1))

#define LDSM4(r0,r1,r2,r3,addr)                                           \
    asm volatile("ldmatrix.sync.aligned.m8n8.x4.shared.b16 {%0,%1,%2,%3}, [%4];" \
        : "=r"(r0), "=r"(r1), "=r"(r2), "=r"(r3) : "r"(addr))

// SW128 swizzle on byte offsets: 16B chunk index ^= row-within-8 (bits[9:7]->[6:4])
__device__ __forceinline__ uint32_t SWZ(uint32_t b) { return b ^ ((b >> 3) & 0x70); }

__device__ __forceinline__ uint32_t smem_u32(const void* p) {
    uint32_t a;
    asm("{ .reg .u64 t; cvta.to.shared.u64 t, %1; cvt.u32.u64 %0, t; }" : "=r"(a) : "l"(p));
    return a;
}

// ---------------- kernel 0: dtype-robust edge decode ----------------
__global__ void edge_decode_kernel(const int* __restrict__ raw) {
    int tid = threadIdx.x;
    int acc = 0;
    for (int i = tid; i < 4096; i += 1024) acc |= raw[2 * i + 1];
    int any_odd = __syncthreads_or(acc != 0);
    bool is64 = (any_odd == 0);
    for (int i = tid; i < 8192; i += 1024)
        g_eraw[i] = is64 ? raw[2 * i] : raw[i];
}

// ---------------- kernel 1: attention diag ----------------
__global__ void diag_kernel(const float* __restrict__ X,
                            const float* __restrict__ w1, const float* __restrict__ b1p,
                            const float* __restrict__ w2, const float* __restrict__ b2p) {
    int nt = blockIdx.x;
    int n = nt >> 9;
    int h = threadIdx.x;
    __shared__ float sa1[64], sw1[64], sw2[64];
    __shared__ int   se[256];
    sw1[h] = w1[h];
    sw2[h] = w2[h];
    const int* ep = g_eraw + n * 512;
#pragma unroll
    for (int i = 0; i < 4; i++) { int e = h + i * 64; se[e] = ep[e] * 64 + ep[256 + e]; }
    __syncthreads();
    const float4* xp = (const float4*)(X + ((size_t)nt * 64 + h) * 64);
    float d1 = 0.f, d2 = 0.f;
#pragma unroll
    for (int c4 = 0; c4 < 16; c4++) {
        float4 x = xp[c4];
        d1 += x.x * sw1[c4 * 4] + x.y * sw1[c4 * 4 + 1] + x.z * sw1[c4 * 4 + 2] + x.w * sw1[c4 * 4 + 3];
        d2 += x.x * sw2[c4 * 4] + x.y * sw2[c4 * 4 + 1] + x.z * sw2[c4 * 4 + 2] + x.w * sw2[c4 * 4 + 3];
    }
    sa1[h] = d1 + b1p[0];
    float a2h = d2 + b2p[0];
    __syncthreads();
    float den = 0.f;
#pragma unroll 8
    for (int k = 0; k < 64; k++) {
        float v = sa1[k] + a2h;
        v = (v > 0.f) ? v : 0.01f * v;
        den += __expf(v);
    }
    float num = 0.f;
    for (int i = 0; i < 256; i++) {
        int rc = se[i];
        if ((rc >> 6) == h) {
            float v = sa1[rc & 63] + a2h;
            v = (v > 0.f) ? v : 0.01f * v;
            num += __expf(v);
        }
    }
    g_diag[(size_t)nt * 64 + h] = num / den + 1.f;
}

// ---------------- persistent fused kernel (ldmatrix + mma.sync conv) --------
#define OFF_WH  0        // conv W hi: 9 taps x [64 rows o][64 op bf16] SW128  73728
#define OFF_WL  73728    // conv W lo                                          73728
#define OFF_YH  147456   // y1 hi: [136 rows t][64 o bf16] SW128               17408
#define OFF_YL  164864   // y1 lo                                              17408
#define OFF_X   182272   // X tile f32 136x64  /  D staging 128x68 f32         34816
#define OFF_DG  217088   // diag[136]                                            544
#define OFF_CON 217632   // inv1|be1|bl|inv2|bet2 (5x64 f32)                    1280
#define SMEM_TOTAL 218912

__global__ void __launch_bounds__(512, 1)
fused_kernel(const float* __restrict__ X,
             const float* __restrict__ Wl, const float* __restrict__ bl,
             const float* __restrict__ g1, const float* __restrict__ be1,
             const float* __restrict__ Wt, const float* __restrict__ bt,
             const float* __restrict__ g2, const float* __restrict__ be2,
             float* __restrict__ out) {
    extern __shared__ char smem[];
    uint32_t sb = smem_u32(smem);
    int tid = threadIdx.x, wid = tid >> 5, lane = tid & 31;
    float* sdg = (float*)(smem + OFF_DG);
    float* con = (float*)(smem + OFF_CON);

    // ---- prologue: pack conv weights hi/lo into SW128 smem ----
    // B matrix for tap kk: row n=o (128B row), k=op (bf16). byte = SWZ(o*128+op*2)
    for (int i = tid; i < 36864; i += 512) {
        int kk = i >> 12, rr = i & 4095, o = rr >> 6, op = rr & 63;
        float w = Wt[(size_t)o * 576 + op * 9 + kk];
        __nv_bfloat16 hi = __float2bfloat16(w);
        __nv_bfloat16 lo = __float2bfloat16(w - __bfloat162float(hi));
        uint32_t off = SWZ(o * 128 + op * 2);
        *(__nv_bfloat16*)(smem + OFF_WH + kk * 8192 + off) = hi;
        *(__nv_bfloat16*)(smem + OFF_WL + kk * 8192 + off) = lo;
    }
    if (tid < 64) {
        float i1 = g1[tid] * rsqrtf(1.f + EPSF);
        float i2 = g2[tid] * rsqrtf(1.f + EPSF);
        con[tid] = i1; con[64 + tid] = be1[tid]; con[128 + tid] = bl[tid];
        con[192 + tid] = i2; con[256 + tid] = be2[tid] + bt[tid] * i2;
    }
    __syncthreads();

    int o = tid & 63, tg = tid >> 6;      // support mapping: 8 row-groups
    const float4* Xg = (const float4*)X;
    const float4* Wl4 = (const float4*)Wl;   // W_lin (O,C) row-major

    for (int item = blockIdx.x; item < 4096; item += gridDim.x) {
        int n = item >> 8, rem = item & 255, h = rem >> 2, t0 = (rem & 3) << 7;

        // ---- load X tile (136 rows x 64 f32) + diag ----
        float4* Xb = (float4*)(smem + OFF_X);
        for (int q = tid; q < 136 * 16; q += 512) {
            int r = q >> 4, c4 = q & 15, t = t0 - 4 + r;
            float4 v = make_float4(0.f, 0.f, 0.f, 0.f);
            if ((unsigned)t < 512u) v = Xg[(((size_t)n * 512 + t) * 64 + h) * 16 + c4];
            Xb[r * 16 + c4] = v;
        }
        for (int q = tid; q < 136; q += 512) {
            int t = t0 - 4 + q;
            sdg[q] = ((unsigned)t < 512u) ? g_diag[((size_t)n * 512 + t) * 64 + h] : 0.f;
        }
        __syncthreads();

        // ---- scalar support GEMM + diag + bn1 + relu ----
        float acc[17];
#pragma unroll
        for (int j = 0; j < 17; j++) acc[j] = 0.f;
#pragma unroll
        for (int c4 = 0; c4 < 16; c4++) {
            float4 wv = __ldg(Wl4 + o * 16 + c4);   // W_lin[o][4c4..] (L1-hot)
#pragma unroll
            for (int j = 0; j < 17; j++) {
                float4 x = Xb[(tg + 8 * j) * 16 + c4];
                acc[j] += x.x * wv.x + x.y * wv.y + x.z * wv.z + x.w * wv.w;
            }
        }
        float i1 = con[o], b1v = con[64 + o], blv = con[128 + o];
#pragma unroll
        for (int j = 0; j < 17; j++) {
            int r = tg + 8 * j, t = t0 - 4 + r;
            float yv = 0.f;
            if ((unsigned)t < 512u)
                yv = fmaxf(sdg[r] * (acc[j] + blv) * i1 + b1v, 0.f);
            acc[j] = yv;
        }
        // ---- write y1 hi/lo (SW128 bf16): byte = SWZ(r*128 + o*2) ----
#pragma unroll
        for (int j = 0; j < 17; j++) {
            int r = tg + 8 * j;
            __nv_bfloat16 hi = __float2bfloat16(acc[j]);
            __nv_bfloat16 lo = __float2bfloat16(acc[j] - __bfloat162float(hi));
            uint32_t off = SWZ(r * 128 + o * 2);
            *(__nv_bfloat16*)(smem + OFF_YH + off) = hi;
            *(__nv_bfloat16*)(smem + OFF_YL + off) = lo;
        }
        __syncthreads();   // y1 complete; X reads complete

        // ---- conv: ldmatrix fragments, B hoisted per kc across 9 taps ----
        {
            int ms = wid >> 1, nh = wid & 1;          // m-stripe (0-7), n-half
            int lr = lane >> 2, lc = lane & 3;
            // ldmatrix lane-address components
            uint32_t rA   = 16 * ms + (lane & 7) + 8 * ((lane >> 3) & 1);
            uint32_t colA = ((lane >> 4) & 1) * 16;
            uint32_t rB   = 32 * nh + 8 * (lane >> 3) + (lane & 7);
            uint32_t yh = sb + OFF_YH, yl = sb + OFF_YL;
            uint32_t whb = sb + OFF_WH, wlb = sb + OFF_WL;

            float C0[4] = {0.f,0.f,0.f,0.f}, C1[4] = {0.f,0.f,0.f,0.f};
            float C2[4] = {0.f,0.f,0.f,0.f}, C3[4] = {0.f,0.f,0.f,0.f};
            float* Cn[4] = {C0, C1, C2, C3};

#pragma unroll
            for (int kc = 0; kc < 4; kc++) {
                // B fragments (4 n-tiles), hoisted across taps
                uint32_t b0off = SWZ(rB * 128 + kc * 32);
                uint32_t b1off = SWZ(rB * 128 + kc * 32 + 16);
                uint32_t bh0[4], bh1[4], bl0[4], bl1[4];
#pragma unroll 1
                for (int kk = 0; kk < 9; kk++) {
                    if (kk == 0) {
                        LDSM4(bh0[0],bh0[1],bh0[2],bh0[3], whb + b0off);
                        LDSM4(bh1[0],bh1[1],bh1[2],bh1[3], whb + b1off);
                        LDSM4(bl0[0],bl0[1],bl0[2],bl0[3], wlb + b0off);
                        LDSM4(bl1[0],bl1[1],bl1[2],bl1[3], wlb + b1off);
                    }
                    uint32_t aoff = SWZ((rA + kk) * 128 + kc * 32 + colA);
                    uint32_t ah0,ah1,ah2,ah3, al0,al1,al2,al3;
                    LDSM4(ah0,ah1,ah2,ah3, yh + aoff);
                    LDSM4(al0,al1,al2,al3, yl + aoff);
#pragma unroll
                    for (int nt = 0; nt < 4; nt++) {
                        MMA16816(Cn[nt], ah0,ah1,ah2,ah3, bh0[nt], bh1[nt]);
                        MMA16816(Cn[nt], ah0,ah1,ah2,ah3, bl0[nt], bl1[nt]);
                        MMA16816(Cn[nt], al0,al1,al2,al3, bh0[nt], bh1[nt]);
                    }
                    // advance B tap base: next kk reuses same regs? B differs per tap!
                    // -> reload B for next tap
                    if (kk < 8) {
                        uint32_t nb0 = b0off + 8192 * (kk + 1);
                        uint32_t nb1 = b1off + 8192 * (kk + 1);
                        LDSM4(bh0[0],bh0[1],bh0[2],bh0[3], whb + nb0);
                        LDSM4(bh1[0],bh1[1],bh1[2],bh1[3], whb + nb1);
                        LDSM4(bl0[0],bl0[1],bl0[2],bl0[3], wlb + nb0);
                        LDSM4(bl1[0],bl1[1],bl1[2],bl1[3], wlb + nb1);
                    }
                }
            }
            // stage D to smem (reuse X region), stride 68 f32
            float* Dst = (float*)(smem + OFF_X);
#pragma unroll
            for (int nt = 0; nt < 4; nt++) {
                int col = 32 * nh + 8 * nt + 2 * lc;
                int row = 16 * ms + lr;
                Dst[row * 68 + col]           = Cn[nt][0];
                Dst[row * 68 + col + 1]       = Cn[nt][1];
                Dst[(row + 8) * 68 + col]     = Cn[nt][2];
                Dst[(row + 8) * 68 + col + 1] = Cn[nt][3];
            }
        }
        __syncthreads();

        // ---- epilogue: bn2 + residual + relu, coalesced float4 stores ----
        {
            const float* Dst = (const float*)(smem + OFF_X);
#pragma unroll
            for (int i = 0; i < 4; i++) {
                int idx = tid + i * 512;
                int row = idx >> 4, c4 = idx & 15;
                float4 dv = *(const float4*)(Dst + row * 68 + 4 * c4);
                size_t gi = (((size_t)n * 512 + t0 + row) * 64 + h) * 16 + c4;
                float4 xv = Xg[gi];
                float4 iv = *(const float4*)(con + 192 + 4 * c4);
                float4 bv = *(const float4*)(con + 256 + 4 * c4);
                float4 rv;
                rv.x = fmaxf(dv.x * iv.x + bv.x + xv.x, 0.f);
                rv.y = fmaxf(dv.y * iv.y + bv.y + xv.y, 0.f);
                rv.z = fmaxf(dv.z * iv.z + bv.z + xv.z, 0.f);
                rv.w = fmaxf(dv.w * iv.w + bv.w + xv.w, 0.f);
                ((float4*)out)[gi] = rv;
            }
        }
        __syncthreads();   // protect smem before next tile overwrites
    }
}

// ---------------- launch ----------------
extern "C" void kernel_launch(void* const* d_in, const int* in_sizes, int n_in,
                              void* d_out, int out_size) {
    const float* X    = (const float*)d_in[0];
    const int*   eraw = (const int*)d_in[1];
    const float* w1   = (const float*)d_in[2];
    const float* b1   = (const float*)d_in[3];
    const float* w2   = (const float*)d_in[4];
    const float* b2   = (const float*)d_in[5];
    const float* Wl   = (const float*)d_in[6];
    const float* bl   = (const float*)d_in[7];
    const float* bn1g = (const float*)d_in[8];
    const float* bn1b = (const float*)d_in[9];
    const float* Wtcn = (const float*)d_in[10];
    const float* btcn = (const float*)d_in[11];
    const float* bn2g = (const float*)d_in[12];
    const float* bn2b = (const float*)d_in[13];
    float* out = (float*)d_out;

    cudaFuncSetAttribute(fused_kernel, cudaFuncAttributeMaxDynamicSharedMemorySize, SMEM_TOTAL);
    edge_decode_kernel<<<1, 1024>>>(eraw);
    diag_kernel<<<16 * 512, 64>>>(X, w1, b1, w2, b2);
    fused_kernel<<<148, 512, SMEM_TOTAL>>>(X, Wl, bl, bn1g, bn1b,
                                           Wtcn, btcn, bn2g, bn2b, out);
}

// round 16
// speedup vs baseline: 1.3276x; 1.3276x over previous
#include <cuda_runtime.h>
#include <cuda_fp16.h>
#include <math.h>
#include <stdint.h>

#define EPSF 1e-5f

__device__ float g_diag[16 * 512 * 64];
__device__ int   g_eraw[16 * 512];

// m16n8k16 fp16 MMA, fp32 accum (baseline PTX, maps to HMMA on sm_103)
#define MMA16816(c, a0,a1,a2,a3, b0,b1)                                   \
    asm volatile("mma.sync.aligned.m16n8k16.row.col.f32.f16.f16.f32 "     \
        "{%0,%1,%2,%3}, {%4,%5,%6,%7}, {%8,%9}, {%0,%1,%2,%3};"           \
        : "+f"((c)[0]), "+f"((c)[1]), "+f"((c)[2]), "+f"((c)[3])          \
        : "r"(a0), "r"(a1), "r"(a2), "r"(a3), "r"(b0), "r"(b1))

#define LDSM4(r0,r1,r2,r3,addr)                                           \
    asm volatile("ldmatrix.sync.aligned.m8n8.x4.shared.b16 {%0,%1,%2,%3}, [%4];" \
        : "=r"(r0), "=r"(r1), "=r"(r2), "=r"(r3) : "r"(addr))

// SW128 swizzle on byte offsets within a 128B-row tile
__device__ __forceinline__ uint32_t SWZ(uint32_t b) { return b ^ ((b >> 3) & 0x70); }

__device__ __forceinline__ uint32_t smem_u32(const void* p) {
    uint32_t a;
    asm("{ .reg .u64 t; cvta.to.shared.u64 t, %1; cvt.u32.u64 %0, t; }" : "=r"(a) : "l"(p));
    return a;
}

// ---------------- kernel 0: dtype-robust edge decode ----------------
__global__ void edge_decode_kernel(const int* __restrict__ raw) {
    int tid = threadIdx.x;
    int acc = 0;
    for (int i = tid; i < 4096; i += 1024) acc |= raw[2 * i + 1];
    int any_odd = __syncthreads_or(acc != 0);
    bool is64 = (any_odd == 0);
    for (int i = tid; i < 8192; i += 1024)
        g_eraw[i] = is64 ? raw[2 * i] : raw[i];
}

// ---------------- kernel 1: attention diag ----------------
__global__ void diag_kernel(const float* __restrict__ X,
                            const float* __restrict__ w1, const float* __restrict__ b1p,
                            const float* __restrict__ w2, const float* __restrict__ b2p) {
    int nt = blockIdx.x;
    int n = nt >> 9;
    int h = threadIdx.x;
    __shared__ float sa1[64], sw1[64], sw2[64];
    __shared__ int   se[256];
    sw1[h] = w1[h];
    sw2[h] = w2[h];
    const int* ep = g_eraw + n * 512;
#pragma unroll
    for (int i = 0; i < 4; i++) { int e = h + i * 64; se[e] = ep[e] * 64 + ep[256 + e]; }
    __syncthreads();
    const float4* xp = (const float4*)(X + ((size_t)nt * 64 + h) * 64);
    float d1 = 0.f, d2 = 0.f;
#pragma unroll
    for (int c4 = 0; c4 < 16; c4++) {
        float4 x = xp[c4];
        d1 += x.x * sw1[c4 * 4] + x.y * sw1[c4 * 4 + 1] + x.z * sw1[c4 * 4 + 2] + x.w * sw1[c4 * 4 + 3];
        d2 += x.x * sw2[c4 * 4] + x.y * sw2[c4 * 4 + 1] + x.z * sw2[c4 * 4 + 2] + x.w * sw2[c4 * 4 + 3];
    }
    sa1[h] = d1 + b1p[0];
    float a2h = d2 + b2p[0];
    __syncthreads();
    float den = 0.f;
#pragma unroll 8
    for (int k = 0; k < 64; k++) {
        float v = sa1[k] + a2h;
        v = (v > 0.f) ? v : 0.01f * v;
        den += __expf(v);
    }
    float num = 0.f;
    for (int i = 0; i < 256; i++) {
        int rc = se[i];
        if ((rc >> 6) == h) {
            float v = sa1[rc & 63] + a2h;
            v = (v > 0.f) ? v : 0.01f * v;
            num += __expf(v);
        }
    }
    g_diag[(size_t)nt * 64 + h] = num / den + 1.f;
}

// ---------------- persistent fused kernel (fp16 single-pass mma conv) -------
#define OFF_WH  0        // conv W fp16: 9 taps x [64 o][64 op] SW128   73728
#define OFF_YH  73728    // y1 fp16: [136 t][64 o] SW128                17408
#define OFF_X   91136    // X tile f32 136x64 / D staging 128x68 f32    34816
#define OFF_DG  125952   // diag[136]                                     544
#define OFF_CON 126496   // inv1|be1|bl|inv2|bet2 (5x64 f32)             1280
#define SMEM_TOTAL 127776

__global__ void __launch_bounds__(512, 1)
fused_kernel(const float* __restrict__ X,
             const float* __restrict__ Wl, const float* __restrict__ bl,
             const float* __restrict__ g1, const float* __restrict__ be1,
             const float* __restrict__ Wt, const float* __restrict__ bt,
             const float* __restrict__ g2, const float* __restrict__ be2,
             float* __restrict__ out) {
    extern __shared__ char smem[];
    uint32_t sb = smem_u32(smem);
    int tid = threadIdx.x, wid = tid >> 5, lane = tid & 31;
    float* sdg = (float*)(smem + OFF_DG);
    float* con = (float*)(smem + OFF_CON);

    // ---- prologue: pack conv weights fp16 into SW128 smem ----
    for (int i = tid; i < 36864; i += 512) {
        int kk = i >> 12, rr = i & 4095, o = rr >> 6, op = rr & 63;
        float w = Wt[(size_t)o * 576 + op * 9 + kk];
        *(__half*)(smem + OFF_WH + kk * 8192 + SWZ(o * 128 + op * 2)) = __float2half(w);
    }
    if (tid < 64) {
        float i1 = g1[tid] * rsqrtf(1.f + EPSF);
        float i2 = g2[tid] * rsqrtf(1.f + EPSF);
        con[tid] = i1; con[64 + tid] = be1[tid]; con[128 + tid] = bl[tid];
        con[192 + tid] = i2; con[256 + tid] = be2[tid] + bt[tid] * i2;
    }
    __syncthreads();

    int o = tid & 63, tg = tid >> 6;      // support mapping: 8 row-groups
    const float4* Xg = (const float4*)X;
    const float4* Wl4 = (const float4*)Wl;   // W_lin (O,C) row-major

    for (int item = blockIdx.x; item < 4096; item += gridDim.x) {
        int n = item >> 8, rem = item & 255, h = rem >> 2, t0 = (rem & 3) << 7;

        // ---- load X tile (136 rows x 64 f32) + diag ----
        float4* Xb = (float4*)(smem + OFF_X);
        for (int q = tid; q < 136 * 16; q += 512) {
            int r = q >> 4, c4 = q & 15, t = t0 - 4 + r;
            float4 v = make_float4(0.f, 0.f, 0.f, 0.f);
            if ((unsigned)t < 512u) v = Xg[(((size_t)n * 512 + t) * 64 + h) * 16 + c4];
            Xb[r * 16 + c4] = v;
        }
        for (int q = tid; q < 136; q += 512) {
            int t = t0 - 4 + q;
            sdg[q] = ((unsigned)t < 512u) ? g_diag[((size_t)n * 512 + t) * 64 + h] : 0.f;
        }
        __syncthreads();

        // ---- scalar support GEMM + diag + bn1 + relu ----
        float acc[17];
#pragma unroll
        for (int j = 0; j < 17; j++) acc[j] = 0.f;
#pragma unroll
        for (int c4 = 0; c4 < 16; c4++) {
            float4 wv = __ldg(Wl4 + o * 16 + c4);   // W_lin[o][4c4..] (L1-hot)
#pragma unroll
            for (int j = 0; j < 17; j++) {
                float4 x = Xb[(tg + 8 * j) * 16 + c4];
                acc[j] += x.x * wv.x + x.y * wv.y + x.z * wv.z + x.w * wv.w;
            }
        }
        float i1 = con[o], b1v = con[64 + o], blv = con[128 + o];
#pragma unroll
        for (int j = 0; j < 17; j++) {
            int r = tg + 8 * j, t = t0 - 4 + r;
            float yv = 0.f;
            if ((unsigned)t < 512u)
                yv = fmaxf(sdg[r] * (acc[j] + blv) * i1 + b1v, 0.f);
            acc[j] = yv;
        }
        // ---- write y1 fp16 (SW128): byte = SWZ(r*128 + o*2) ----
#pragma unroll
        for (int j = 0; j < 17; j++) {
            int r = tg + 8 * j;
            *(__half*)(smem + OFF_YH + SWZ(r * 128 + o * 2)) = __float2half(acc[j]);
        }
        __syncthreads();   // y1 complete; X reads complete

        // ---- conv: ldmatrix fragments, single fp16 pass ----
        {
            int ms = wid >> 1, nh = wid & 1;          // m-stripe (0-7), n-half
            int lr = lane >> 2, lc = lane & 3;
            uint32_t rA   = 16 * ms + (lane & 7) + 8 * ((lane >> 3) & 1);
            uint32_t colA = ((lane >> 4) & 1) * 16;
            uint32_t rB   = 32 * nh + 8 * (lane >> 3) + (lane & 7);
            uint32_t yh = sb + OFF_YH, whb = sb + OFF_WH;

            float C0[4] = {0.f,0.f,0.f,0.f}, C1[4] = {0.f,0.f,0.f,0.f};
            float C2[4] = {0.f,0.f,0.f,0.f}, C3[4] = {0.f,0.f,0.f,0.f};
            float* Cn[4] = {C0, C1, C2, C3};

#pragma unroll
            for (int kc = 0; kc < 4; kc++) {
                uint32_t b0off = SWZ(rB * 128 + kc * 32);
                uint32_t b1off = SWZ(rB * 128 + kc * 32 + 16);
#pragma unroll 1
                for (int kk = 0; kk < 9; kk++) {
                    uint32_t b0[4], b1[4];
                    LDSM4(b0[0],b0[1],b0[2],b0[3], whb + kk * 8192 + b0off);
                    LDSM4(b1[0],b1[1],b1[2],b1[3], whb + kk * 8192 + b1off);
                    uint32_t a0,a1,a2,a3;
                    LDSM4(a0,a1,a2,a3, yh + SWZ((rA + kk) * 128 + kc * 32 + colA));
#pragma unroll
                    for (int nt = 0; nt < 4; nt++)
                        MMA16816(Cn[nt], a0,a1,a2,a3, b0[nt], b1[nt]);
                }
            }
            // stage D to smem (reuse X region), stride 68 f32
            float* Dst = (float*)(smem + OFF_X);
#pragma unroll
            for (int nt = 0; nt < 4; nt++) {
                int col = 32 * nh + 8 * nt + 2 * lc;
                int row = 16 * ms + lr;
                Dst[row * 68 + col]           = Cn[nt][0];
                Dst[row * 68 + col + 1]       = Cn[nt][1];
                Dst[(row + 8) * 68 + col]     = Cn[nt][2];
                Dst[(row + 8) * 68 + col + 1] = Cn[nt][3];
            }
        }
        __syncthreads();

        // ---- epilogue: bn2 + residual + relu, coalesced float4 stores ----
        {
            const float* Dst = (const float*)(smem + OFF_X);
#pragma unroll
            for (int i = 0; i < 4; i++) {
                int idx = tid + i * 512;
                int row = idx >> 4, c4 = idx & 15;
                float4 dv = *(const float4*)(Dst + row * 68 + 4 * c4);
                size_t gi = (((size_t)n * 512 + t0 + row) * 64 + h) * 16 + c4;
                float4 xv = Xg[gi];
                float4 iv = *(const float4*)(con + 192 + 4 * c4);
                float4 bv = *(const float4*)(con + 256 + 4 * c4);
                float4 rv;
                rv.x = fmaxf(dv.x * iv.x + bv.x + xv.x, 0.f);
                rv.y = fmaxf(dv.y * iv.y + bv.y + xv.y, 0.f);
                rv.z = fmaxf(dv.z * iv.z + bv.z + xv.z, 0.f);
                rv.w = fmaxf(dv.w * iv.w + bv.w + xv.w, 0.f);
                ((float4*)out)[gi] = rv;
            }
        }
        __syncthreads();   // protect smem before next tile overwrites
    }
}

// ---------------- launch ----------------
extern "C" void kernel_launch(void* const* d_in, const int* in_sizes, int n_in,
                              void* d_out, int out_size) {
    const float* X    = (const float*)d_in[0];
    const int*   eraw = (const int*)d_in[1];
    const float* w1   = (const float*)d_in[2];
    const float* b1   = (const float*)d_in[3];
    const float* w2   = (const float*)d_in[4];
    const float* b2   = (const float*)d_in[5];
    const float* Wl   = (const float*)d_in[6];
    const float* bl   = (const float*)d_in[7];
    const float* bn1g = (const float*)d_in[8];
    const float* bn1b = (const float*)d_in[9];
    const float* Wtcn = (const float*)d_in[10];
    const float* btcn = (const float*)d_in[11];
    const float* bn2g = (const float*)d_in[12];
    const float* bn2b = (const float*)d_in[13];
    float* out = (float*)d_out;

    cudaFuncSetAttribute(fused_kernel, cudaFuncAttributeMaxDynamicSharedMemorySize, SMEM_TOTAL);
    edge_decode_kernel<<<1, 1024>>>(eraw);
    diag_kernel<<<16 * 512, 64>>>(X, w1, b1, w2, b2);
    fused_kernel<<<148, 512, SMEM_TOTAL>>>(X, Wl, bl, bn1g, bn1b,
                                           Wtcn, btcn, bn2g, bn2b, out);
}

// round 17
// speedup vs baseline: 1.8442x; 1.3892x over previous
#include <cuda_runtime.h>
#include <cuda_fp16.h>
#include <math.h>
#include <stdint.h>

#define EPSF 1e-5f

__device__ float g_diag[16 * 512 * 64];
__device__ int   g_eraw[16 * 512];

#define MMA16816(c, a0,a1,a2,a3, b0,b1)                                   \
    asm volatile("mma.sync.aligned.m16n8k16.row.col.f32.f16.f16.f32 "     \
        "{%0,%1,%2,%3}, {%4,%5,%6,%7}, {%8,%9}, {%0,%1,%2,%3};"           \
        : "+f"((c)[0]), "+f"((c)[1]), "+f"((c)[2]), "+f"((c)[3])          \
        : "r"(a0), "r"(a1), "r"(a2), "r"(a3), "r"(b0), "r"(b1))

#define LDSM4(r0,r1,r2,r3,addr)                                           \
    asm volatile("ldmatrix.sync.aligned.m8n8.x4.shared.b16 {%0,%1,%2,%3}, [%4];" \
        : "=r"(r0), "=r"(r1), "=r"(r2), "=r"(r3) : "r"(addr))

__device__ __forceinline__ uint32_t SWZ(uint32_t b) { return b ^ ((b >> 3) & 0x70); }

__device__ __forceinline__ uint32_t smem_u32(const void* p) {
    uint32_t a;
    asm("{ .reg .u64 t; cvta.to.shared.u64 t, %1; cvt.u32.u64 %0, t; }" : "=r"(a) : "l"(p));
    return a;
}

// ---------------- kernel 0: dtype-robust edge decode ----------------
__global__ void edge_decode_kernel(const int* __restrict__ raw) {
    int tid = threadIdx.x;
    int acc = 0;
    for (int i = tid; i < 4096; i += 1024) acc |= raw[2 * i + 1];
    int any_odd = __syncthreads_or(acc != 0);
    bool is64 = (any_odd == 0);
    for (int i = tid; i < 8192; i += 1024)
        g_eraw[i] = is64 ? raw[2 * i] : raw[i];
}

// ---------------- kernel 1: attention diag ----------------
__global__ void diag_kernel(const float* __restrict__ X,
                            const float* __restrict__ w1, const float* __restrict__ b1p,
                            const float* __restrict__ w2, const float* __restrict__ b2p) {
    int nt = blockIdx.x;
    int n = nt >> 9;
    int h = threadIdx.x;
    __shared__ float sa1[64], sw1[64], sw2[64];
    __shared__ int   se[256];
    sw1[h] = w1[h];
    sw2[h] = w2[h];
    const int* ep = g_eraw + n * 512;
#pragma unroll
    for (int i = 0; i < 4; i++) { int e = h + i * 64; se[e] = ep[e] * 64 + ep[256 + e]; }
    __syncthreads();
    const float4* xp = (const float4*)(X + ((size_t)nt * 64 + h) * 64);
    float d1 = 0.f, d2 = 0.f;
#pragma unroll
    for (int c4 = 0; c4 < 16; c4++) {
        float4 x = xp[c4];
        d1 += x.x * sw1[c4 * 4] + x.y * sw1[c4 * 4 + 1] + x.z * sw1[c4 * 4 + 2] + x.w * sw1[c4 * 4 + 3];
        d2 += x.x * sw2[c4 * 4] + x.y * sw2[c4 * 4 + 1] + x.z * sw2[c4 * 4 + 2] + x.w * sw2[c4 * 4 + 3];
    }
    sa1[h] = d1 + b1p[0];
    float a2h = d2 + b2p[0];
    __syncthreads();
    float den = 0.f;
#pragma unroll 8
    for (int k = 0; k < 64; k++) {
        float v = sa1[k] + a2h;
        v = (v > 0.f) ? v : 0.01f * v;
        den += __expf(v);
    }
    float num = 0.f;
    for (int i = 0; i < 256; i++) {
        int rc = se[i];
        if ((rc >> 6) == h) {
            float v = sa1[rc & 63] + a2h;
            v = (v > 0.f) ? v : 0.01f * v;
            num += __expf(v);
        }
    }
    g_diag[(size_t)nt * 64 + h] = num / den + 1.f;
}

// ---------------- persistent fused kernel (full-MMA pipeline) ----------------
#define OFF_WH   0        // conv W fp16: 9 taps x [64 o][64 op] SW128     73728
#define OFF_WLH  73728    // W_lin hi fp16 [64 o][64 c] SW128               8192
#define OFF_WLL  81920    // W_lin lo                                       8192
#define OFF_XH   90112    // X hi fp16 [144 r][64 c] SW128 / D stage f32   18432
#define OFF_XL   108544   // X lo                                          18432
#define OFF_YH   126976   // y1 fp16 [144 r][64 o] SW128                   18432
#define OFF_DG   145408   // diag[144]                                       576
#define OFF_CON  145984   // inv1|be1|bl|inv2|bet2 (5x64 f32)               1280
#define SMEM_TOTAL 147264
#define OFF_D    OFF_XH   // D staging 128x68 f32 (34816 <= 36864) overlaps X

__global__ void __launch_bounds__(512, 1)
fused_kernel(const float* __restrict__ X,
             const float* __restrict__ Wl, const float* __restrict__ bl,
             const float* __restrict__ g1, const float* __restrict__ be1,
             const float* __restrict__ Wt, const float* __restrict__ bt,
             const float* __restrict__ g2, const float* __restrict__ be2,
             float* __restrict__ out) {
    extern __shared__ char smem[];
    uint32_t sb = smem_u32(smem);
    int tid = threadIdx.x, wid = tid >> 5, lane = tid & 31;
    float* sdg = (float*)(smem + OFF_DG);
    float* con = (float*)(smem + OFF_CON);

    // ---- prologue: conv W fp16, W_lin hi/lo fp16 (both SW128) ----
    for (int i = tid; i < 36864; i += 512) {
        int kk = i >> 12, rr = i & 4095, o = rr >> 6, op = rr & 63;
        float w = Wt[(size_t)o * 576 + op * 9 + kk];
        *(__half*)(smem + OFF_WH + kk * 8192 + SWZ(o * 128 + op * 2)) = __float2half(w);
    }
    for (int i = tid; i < 4096; i += 512) {
        int o = i >> 6, c = i & 63;
        float w = Wl[o * 64 + c];
        __half hi = __float2half(w);
        __half lo = __float2half(w - __half2float(hi));
        uint32_t off = SWZ(o * 128 + c * 2);
        *(__half*)(smem + OFF_WLH + off) = hi;
        *(__half*)(smem + OFF_WLL + off) = lo;
    }
    if (tid < 64) {
        float i1 = g1[tid] * rsqrtf(1.f + EPSF);
        float i2 = g2[tid] * rsqrtf(1.f + EPSF);
        con[tid] = i1; con[64 + tid] = be1[tid]; con[128 + tid] = bl[tid];
        con[192 + tid] = i2; con[256 + tid] = be2[tid] + bt[tid] * i2;
    }
    __syncthreads();

    const float4* Xg = (const float4*)X;
    int lr = lane >> 2, lc = lane & 3;
    // ldmatrix lane-address row components (shared by support + conv)
    uint32_t laneR = (lane & 7) + 8 * ((lane >> 3) & 1);
    uint32_t colA  = ((lane >> 4) & 1) * 16;
    uint32_t laneRB = 8 * (lane >> 3) + (lane & 7);

    for (int item = blockIdx.x; item < 4096; item += gridDim.x) {
        int n = item >> 8, rem = item & 255, h = rem >> 2, t0 = (rem & 3) << 7;

        // ---- load X, split to fp16 hi/lo SW128 (144 rows: 8 pad) + diag ----
        for (int q = tid; q < 144 * 16; q += 512) {
            int r = q >> 4, c4 = q & 15, t = t0 - 4 + r;
            float4 v = make_float4(0.f, 0.f, 0.f, 0.f);
            if ((unsigned)t < 512u) v = Xg[(((size_t)n * 512 + t) * 64 + h) * 16 + c4];
            __half h0 = __float2half(v.x), h1 = __float2half(v.y);
            __half h2 = __float2half(v.z), h3 = __float2half(v.w);
            __half l0 = __float2half(v.x - __half2float(h0));
            __half l1 = __float2half(v.y - __half2float(h1));
            __half l2 = __float2half(v.z - __half2float(h2));
            __half l3 = __float2half(v.w - __half2float(h3));
            uint32_t off = SWZ(r * 128 + c4 * 8);
            *(uint2*)(smem + OFF_XH + off) = make_uint2(
                (uint32_t)__half_as_ushort(h0) | ((uint32_t)__half_as_ushort(h1) << 16),
                (uint32_t)__half_as_ushort(h2) | ((uint32_t)__half_as_ushort(h3) << 16));
            *(uint2*)(smem + OFF_XL + off) = make_uint2(
                (uint32_t)__half_as_ushort(l0) | ((uint32_t)__half_as_ushort(l1) << 16),
                (uint32_t)__half_as_ushort(l2) | ((uint32_t)__half_as_ushort(l3) << 16));
        }
        for (int q = tid; q < 144; q += 512) {
            int t = t0 - 4 + q;
            sdg[q] = ((unsigned)t < 512u) ? g_diag[((size_t)n * 512 + t) * 64 + h] : 0.f;
        }
        __syncthreads();

        // ---- support GEMM as 3-pass fp16 MMA + fragment epilogue -> y1 ----
        {
            uint32_t xh = sb + OFF_XH, xl = sb + OFF_XL;
            uint32_t wlh = sb + OFF_WLH, wll = sb + OFF_WLL;
#pragma unroll 1
            for (int rep = 0; rep < 2; rep++) {
                int u = (rep == 0) ? wid : (16 + wid);
                if (u >= 18) break;
                int ms9 = u >> 1, nh2 = u & 1;
                uint32_t rA = 16 * ms9 + laneR;
                uint32_t rB = 32 * nh2 + laneRB;
                float S0[4] = {0,0,0,0}, S1[4] = {0,0,0,0};
                float S2[4] = {0,0,0,0}, S3[4] = {0,0,0,0};
                float* Sn[4] = {S0, S1, S2, S3};
#pragma unroll
                for (int kc = 0; kc < 4; kc++) {
                    uint32_t aoff = SWZ(rA * 128 + kc * 32 + colA);
                    uint32_t ah0,ah1,ah2,ah3, al0,al1,al2,al3;
                    LDSM4(ah0,ah1,ah2,ah3, xh + aoff);
                    LDSM4(al0,al1,al2,al3, xl + aoff);
                    uint32_t b0off = SWZ(rB * 128 + kc * 32);
                    uint32_t b1off = SWZ(rB * 128 + kc * 32 + 16);
                    uint32_t bh0[4], bh1[4], bl0[4], bl1[4];
                    LDSM4(bh0[0],bh0[1],bh0[2],bh0[3], wlh + b0off);
                    LDSM4(bh1[0],bh1[1],bh1[2],bh1[3], wlh + b1off);
                    LDSM4(bl0[0],bl0[1],bl0[2],bl0[3], wll + b0off);
                    LDSM4(bl1[0],bl1[1],bl1[2],bl1[3], wll + b1off);
#pragma unroll
                    for (int nt = 0; nt < 4; nt++) {
                        MMA16816(Sn[nt], ah0,ah1,ah2,ah3, bh0[nt], bh1[nt]);
                        MMA16816(Sn[nt], ah0,ah1,ah2,ah3, bl0[nt], bl1[nt]);
                        MMA16816(Sn[nt], al0,al1,al2,al3, bh0[nt], bh1[nt]);
                    }
                }
                // fragment epilogue: diag * (acc + bl) * inv1 + be1, relu -> YH
                int r0 = 16 * ms9 + lr, r1 = r0 + 8;
                int tA = t0 - 4 + r0, tB = t0 - 4 + r1;
                float dA = sdg[r0], dB = sdg[r1];
                bool inA = ((unsigned)tA < 512u), inB = ((unsigned)tB < 512u);
#pragma unroll
                for (int nt = 0; nt < 4; nt++) {
                    int c0 = 32 * nh2 + 8 * nt + 2 * lc;
                    float i1a = con[c0], i1b = con[c0 + 1];
                    float bea = con[64 + c0], beb = con[64 + c0 + 1];
                    float bla = con[128 + c0], blb = con[128 + c0 + 1];
                    float y0 = inA ? fmaxf(dA * (Sn[nt][0] + bla) * i1a + bea, 0.f) : 0.f;
                    float y1 = inA ? fmaxf(dA * (Sn[nt][1] + blb) * i1b + beb, 0.f) : 0.f;
                    float y2 = inB ? fmaxf(dB * (Sn[nt][2] + bla) * i1a + bea, 0.f) : 0.f;
                    float y3 = inB ? fmaxf(dB * (Sn[nt][3] + blb) * i1b + beb, 0.f) : 0.f;
                    uint32_t p01 = (uint32_t)__half_as_ushort(__float2half(y0))
                                 | ((uint32_t)__half_as_ushort(__float2half(y1)) << 16);
                    uint32_t p23 = (uint32_t)__half_as_ushort(__float2half(y2))
                                 | ((uint32_t)__half_as_ushort(__float2half(y3)) << 16);
                    *(uint32_t*)(smem + OFF_YH + SWZ(r0 * 128 + c0 * 2)) = p01;
                    *(uint32_t*)(smem + OFF_YH + SWZ(r1 * 128 + c0 * 2)) = p23;
                }
            }
        }
        __syncthreads();   // y1 complete; X fragments consumed

        // ---- conv: single fp16 pass, ldmatrix fragments ----
        {
            int ms = wid >> 1, nh = wid & 1;
            uint32_t rA = 16 * ms + laneR;
            uint32_t rB = 32 * nh + laneRB;
            uint32_t yh = sb + OFF_YH, whb = sb + OFF_WH;

            float C0[4] = {0,0,0,0}, C1[4] = {0,0,0,0};
            float C2[4] = {0,0,0,0}, C3[4] = {0,0,0,0};
            float* Cn[4] = {C0, C1, C2, C3};

#pragma unroll
            for (int kc = 0; kc < 4; kc++) {
                uint32_t b0off = SWZ(rB * 128 + kc * 32);
                uint32_t b1off = SWZ(rB * 128 + kc * 32 + 16);
#pragma unroll 1
                for (int kk = 0; kk < 9; kk++) {
                    uint32_t b0[4], b1[4];
                    LDSM4(b0[0],b0[1],b0[2],b0[3], whb + kk * 8192 + b0off);
                    LDSM4(b1[0],b1[1],b1[2],b1[3], whb + kk * 8192 + b1off);
                    uint32_t a0,a1,a2,a3;
                    LDSM4(a0,a1,a2,a3, yh + SWZ((rA + kk) * 128 + kc * 32 + colA));
#pragma unroll
                    for (int nt = 0; nt < 4; nt++)
                        MMA16816(Cn[nt], a0,a1,a2,a3, b0[nt], b1[nt]);
                }
            }
            __syncthreads();   // X/D region: X fp16 no longer needed
            float* Dst = (float*)(smem + OFF_D);
#pragma unroll
            for (int nt = 0; nt < 4; nt++) {
                int col = 32 * nh + 8 * nt + 2 * lc;
                int row = 16 * ms + lr;
                Dst[row * 68 + col]           = Cn[nt][0];
                Dst[row * 68 + col + 1]       = Cn[nt][1];
                Dst[(row + 8) * 68 + col]     = Cn[nt][2];
                Dst[(row + 8) * 68 + col + 1] = Cn[nt][3];
            }
        }
        __syncthreads();

        // ---- epilogue: bn2 + residual + relu, coalesced float4 stores ----
        {
            const float* Dst = (const float*)(smem + OFF_D);
#pragma unroll
            for (int i = 0; i < 4; i++) {
                int idx = tid + i * 512;
                int row = idx >> 4, c4 = idx & 15;
                float4 dv = *(const float4*)(Dst + row * 68 + 4 * c4);
                size_t gi = (((size_t)n * 512 + t0 + row) * 64 + h) * 16 + c4;
                float4 xv = Xg[gi];
                float4 iv = *(const float4*)(con + 192 + 4 * c4);
                float4 bv = *(const float4*)(con + 256 + 4 * c4);
                float4 rv;
                rv.x = fmaxf(dv.x * iv.x + bv.x + xv.x, 0.f);
                rv.y = fmaxf(dv.y * iv.y + bv.y + xv.y, 0.f);
                rv.z = fmaxf(dv.z * iv.z + bv.z + xv.z, 0.f);
                rv.w = fmaxf(dv.w * iv.w + bv.w + xv.w, 0.f);
                ((float4*)out)[gi] = rv;
            }
        }
        __syncthreads();   // protect smem before next tile overwrites
    }
}

// ---------------- launch ----------------
extern "C" void kernel_launch(void* const* d_in, const int* in_sizes, int n_in,
                              void* d_out, int out_size) {
    const float* X    = (const float*)d_in[0];
    const int*   eraw = (const int*)d_in[1];
    const float* w1   = (const float*)d_in[2];
    const float* b1   = (const float*)d_in[3];
    const float* w2   = (const float*)d_in[4];
    const float* b2   = (const float*)d_in[5];
    const float* Wl   = (const float*)d_in[6];
    const float* bl   = (const float*)d_in[7];
    const float* bn1g = (const float*)d_in[8];
    const float* bn1b = (const float*)d_in[9];
    const float* Wtcn = (const float*)d_in[10];
    const float* btcn = (const float*)d_in[11];
    const float* bn2g = (const float*)d_in[12];
    const float* bn2b = (const float*)d_in[13];
    float* out = (float*)d_out;

    cudaFuncSetAttribute(fused_kernel, cudaFuncAttributeMaxDynamicSharedMemorySize, SMEM_TOTAL);
    edge_decode_kernel<<<1, 1024>>>(eraw);
    diag_kernel<<<16 * 512, 64>>>(X, w1, b1, w2, b2);
    fused_kernel<<<148, 512, SMEM_TOTAL>>>(X, Wl, bl, bn1g, bn1b,
                                           Wtcn, btcn, bn2g, bn2b, out);
}